// round 5
// baseline (speedup 1.0000x reference)
#include <cuda_runtime.h>
#include <math.h>
#include <stdint.h>

#define NSLICE 1088          // 64 * 17 slices per tensor
#define HW     16384         // 128 * 128
#define MAX_DIST 181.02f
#define NCTA 148
#define NTH  512
#define CHUNK_FLOATS 8192    // 32 KB chunks, 2 per slice
#define CHUNK_BYTES  32768
#define NRING 5              // 5-deep chunk ring (160 KB) + 64 KB table = 224 KB

__device__ float g_table[HW];      // (|dy|,|dx|) -> sqrt(dy^2+dx^2)
__device__ float g_d[2 * NSLICE];  // per-slice normalized mean distance

// ---------------------------------------------------------------------------
// Kernel 1: build the 128x128 distance table in global memory.
// ---------------------------------------------------------------------------
__global__ void build_table_kernel() {
    int i = blockIdx.x * 256 + threadIdx.x;   // grid = 64 * 256 = 16384
    int dy = i >> 7;
    int dx = i & 127;
    g_table[i] = sqrtf((float)(dy * dy + dx * dx));
}

// ---------------------------------------------------------------------------
// mbarrier / bulk-copy helpers
// ---------------------------------------------------------------------------
__device__ __forceinline__ uint32_t smem_u32(const void* p) {
    return (uint32_t)__cvta_generic_to_shared(p);
}
__device__ __forceinline__ void mbar_init(uint32_t a, uint32_t cnt) {
    asm volatile("mbarrier.init.shared::cta.b64 [%0], %1;" :: "r"(a), "r"(cnt) : "memory");
}
__device__ __forceinline__ void mbar_arrive_expect(uint32_t a, uint32_t bytes) {
    asm volatile("mbarrier.arrive.expect_tx.shared::cta.b64 _, [%0], %1;"
                 :: "r"(a), "r"(bytes) : "memory");
}
__device__ __forceinline__ void bulk_g2s(uint32_t dst, const void* src,
                                         uint32_t bytes, uint32_t mbar) {
    asm volatile("cp.async.bulk.shared::cta.global.mbarrier::complete_tx::bytes "
                 "[%0], [%1], %2, [%3];"
                 :: "r"(dst), "l"(src), "r"(bytes), "r"(mbar) : "memory");
}
__device__ __forceinline__ void mbar_wait(uint32_t a, uint32_t parity) {
    asm volatile(
        "{\n\t.reg .pred P;\n\t"
        "WAIT_%=:\n\t"
        "mbarrier.try_wait.parity.shared::cta.b64 P, [%0], %1;\n\t"
        "@!P bra WAIT_%=;\n\t}"
        :: "r"(a), "r"(parity) : "memory");
}

// ---------------------------------------------------------------------------
// Kernel 2: persistent CTAs over ONE tensor (1088 slices). 5-deep 32KB chunk
// ring via cp.async.bulk; f32 distance table in smem; slice values held in
// registers between pass 1 (max/argmax) and pass 2 (masked distance sum).
// Results written to g_d[dofs + slice].
// ---------------------------------------------------------------------------
__global__ void __launch_bounds__(NTH, 1) slice_kernel(const float* __restrict__ src,
                                                       int dofs) {
    extern __shared__ float smem[];
    float* tab = smem;                         // 16384 floats
    float* ring = smem + HW;                   // NRING * 8192 floats

    __shared__ __align__(8) unsigned long long mbar_store[NRING];
    __shared__ float s_v[16];
    __shared__ int   s_i[16];
    __shared__ float s_s[16];
    __shared__ int   s_c[16];

    const int t = threadIdx.x;
    const int warp = t >> 5, lane = t & 31;
    const int cta = blockIdx.x;
    const int n = (NSLICE - cta + NCTA - 1) / NCTA;   // 7 or 8 slices
    const int nchunk = 2 * n;

    uint32_t mb[NRING];
    #pragma unroll
    for (int r = 0; r < NRING; ++r) mb[r] = smem_u32(&mbar_store[r]);

    if (t == 0) {
        #pragma unroll
        for (int r = 0; r < NRING; ++r) mbar_init(mb[r], 1);
    }
    __syncthreads();

    // chunk k (k = 0..nchunk-1): slice (k>>1), half (k&1)
    auto chunk_src = [&](int k) -> const float* {
        return src + (size_t)(cta + (size_t)(k >> 1) * NCTA) * HW
                   + (size_t)(k & 1) * CHUNK_FLOATS;
    };

    // prefill the ring
    if (t == 0) {
        #pragma unroll
        for (int k = 0; k < NRING; ++k) {
            if (k < nchunk) {
                mbar_arrive_expect(mb[k], CHUNK_BYTES);
                bulk_g2s(smem_u32(ring + k * CHUNK_FLOATS), chunk_src(k),
                         CHUNK_BYTES, mb[k]);
            }
        }
    }

    // table -> smem (overlaps the first chunk fetches)
    {
        const float4* gt = (const float4*)g_table;
        float4* st = (float4*)tab;
        #pragma unroll
        for (int k = 0; k < 8; ++k) st[k * NTH + t] = __ldg(gt + k * NTH + t);
    }

    for (int j = 0; j < n; ++j) {
        float4 v[8];
        float vmax = -1e30f;
        int   vidx = 0x7fffffff;

        // ---------- pass 1: two chunks -> regs, max + lowest flat index -----
        #pragma unroll
        for (int c = 0; c < 2; ++c) {
            const int k = 2 * j + c;
            const int slot = k % NRING;
            mbar_wait(mb[slot], (k / NRING) & 1);

            const float4* bf4 = (const float4*)(ring + slot * CHUNK_FLOATS);
            #pragma unroll
            for (int r = 0; r < 4; ++r) {
                float4 x = bf4[r * NTH + t];
                v[c * 4 + r] = x;
                int e = c * CHUNK_FLOATS + ((r * NTH + t) << 2);
                float m = fmaxf(fmaxf(x.x, x.y), fmaxf(x.z, x.w));
                if (m > vmax) {                 // tree max, single serial update
                    int sel = (x.x == m) ? 0 : (x.y == m) ? 1 : (x.z == m) ? 2 : 3;
                    vmax = m;
                    vidx = e + sel;
                }
            }
            __syncthreads();                    // chunk fully consumed
            if (t == 0 && k + NRING < nchunk) { // refill freed slot
                mbar_arrive_expect(mb[slot], CHUNK_BYTES);
                bulk_g2s(smem_u32(ring + slot * CHUNK_FLOATS),
                         chunk_src(k + NRING), CHUNK_BYTES, mb[slot]);
            }
        }

        #pragma unroll
        for (int off = 16; off > 0; off >>= 1) {
            float ov = __shfl_down_sync(0xffffffffu, vmax, off);
            int   oi = __shfl_down_sync(0xffffffffu, vidx, off);
            if (ov > vmax || (ov == vmax && oi < vidx)) { vmax = ov; vidx = oi; }
        }
        if (lane == 0) { s_v[warp] = vmax; s_i[warp] = vidx; }
        __syncthreads();
        float bv = s_v[0]; int bi = s_i[0];
        #pragma unroll
        for (int w = 1; w < 16; ++w) {
            float wv = s_v[w]; int wi = s_i[w];
            if (wv > bv || (wv == bv && wi < bi)) { bv = wv; bi = wi; }
        }

        // ---------- pass 2: masked distance sum (regs + smem table) ---------
        const float thr = bv * 0.5f;
        const int ym = bi >> 7;
        const int xm = bi & 127;
        float sum = 0.0f;
        int   cnt = 0;
        #pragma unroll
        for (int k = 0; k < 8; ++k) {
            int e = (k >> 2) * CHUNK_FLOATS + (((k & 3) * NTH + t) << 2);
            int y = e >> 7;                     // 4 components share the row
            const float* row = tab + (::abs(y - ym) << 7);
            int x0 = e & 127;
            float d0 = row[::abs(x0     - xm)];
            float d1 = row[::abs(x0 + 1 - xm)];
            float d2 = row[::abs(x0 + 2 - xm)];
            float d3 = row[::abs(x0 + 3 - xm)];
            bool m0 = v[k].x > thr, m1 = v[k].y > thr;
            bool m2 = v[k].z > thr, m3 = v[k].w > thr;
            sum += m0 ? d0 : 0.0f;  cnt += m0;
            sum += m1 ? d1 : 0.0f;  cnt += m1;
            sum += m2 ? d2 : 0.0f;  cnt += m2;
            sum += m3 ? d3 : 0.0f;  cnt += m3;
        }
        #pragma unroll
        for (int off = 16; off > 0; off >>= 1) {
            sum += __shfl_down_sync(0xffffffffu, sum, off);
            cnt += __shfl_down_sync(0xffffffffu, cnt, off);
        }
        if (lane == 0) { s_s[warp] = sum; s_c[warp] = cnt; }
        __syncthreads();
        if (t == 0) {
            float S = 0.0f; int C = 0;
            #pragma unroll
            for (int w = 0; w < 16; ++w) { S += s_s[w]; C += s_c[w]; }
            float d;
            if (bv > 0.0f) {
                d = (C > 0) ? (S / (float)C) / MAX_DIST : 1.0f;
            } else {
                d = 0.0f;
            }
            g_d[dofs + cta + j * NCTA] = d;    // __device__ symbol, device-side
        }
        __syncthreads();                        // s_v/s_s reused next iteration
    }
}

// ---------------------------------------------------------------------------
// Kernel 3: loss = sum |d_a - d_b| / J / B
// ---------------------------------------------------------------------------
__global__ void __launch_bounds__(256) finalize_kernel(float* __restrict__ out) {
    const int t = threadIdx.x;
    float acc = 0.0f;
    for (int i = t; i < NSLICE; i += 256)
        acc += fabsf(g_d[i] - g_d[i + NSLICE]);
    #pragma unroll
    for (int off = 16; off > 0; off >>= 1)
        acc += __shfl_down_sync(0xffffffffu, acc, off);
    __shared__ float sw[8];
    if ((t & 31) == 0) sw[t >> 5] = acc;
    __syncthreads();
    if (t == 0) {
        float S = 0.0f;
        #pragma unroll
        for (int w = 0; w < 8; ++w) S += sw[w];
        out[0] = S / 17.0f / 64.0f;
    }
}

extern "C" void kernel_launch(void* const* d_in, const int* in_sizes, int n_in,
                              void* d_out, int out_size) {
    const float* a = (const float*)d_in[0];   // output heatmaps [64,17,128,128] f32
    const float* b = (const float*)d_in[1];   // target heatmaps [64,17,128,128] f32
    (void)in_sizes; (void)n_in; (void)out_size;

    const int smem_bytes = (HW + NRING * CHUNK_FLOATS) * 4;   // 224 KB

    static bool attr_set = false;
    if (!attr_set) {
        cudaFuncSetAttribute(slice_kernel,
                             cudaFuncAttributeMaxDynamicSharedMemorySize, smem_bytes);
        attr_set = true;
    }

    build_table_kernel<<<64, 256>>>();
    slice_kernel<<<NCTA, NTH, smem_bytes>>>(a, 0);        // tensor "output"
    slice_kernel<<<NCTA, NTH, smem_bytes>>>(b, NSLICE);   // tensor "target"
    finalize_kernel<<<1, 256>>>((float*)d_out);
}

// round 6
// speedup vs baseline: 1.2761x; 1.2761x over previous
#include <cuda_runtime.h>
#include <math.h>
#include <stdint.h>

#define NSLICE 1088          // 64 * 17 slices per tensor
#define HW     16384         // 128 * 128
#define MAX_DIST 181.02f
#define NCTA 148
#define NTH  512
#define CHUNK_FLOATS 8192    // 32 KB chunks, 2 per slice (rows 0-63 / 64-127)
#define CHUNK_BYTES  32768
#define NRING 5              // 160 KB ring + 64 KB table = 224 KB smem

__device__ float g_table[HW];      // (|dy|,|dx|) -> sqrt(dy^2+dx^2)
__device__ float g_acc;            // global loss accumulator
__device__ unsigned int g_done;    // CTA completion counter

// ---------------------------------------------------------------------------
// Kernel 1: build distance table + reset accumulators (re-runs every replay).
// ---------------------------------------------------------------------------
__global__ void build_table_kernel() {
    int i = blockIdx.x * 256 + threadIdx.x;   // 64 * 256 = 16384
    if (i == 0) { g_acc = 0.0f; g_done = 0u; }
    int dy = i >> 7;
    int dx = i & 127;
    g_table[i] = sqrtf((float)(dy * dy + dx * dx));
}

// ---------------------------------------------------------------------------
// mbarrier / bulk-copy helpers
// ---------------------------------------------------------------------------
__device__ __forceinline__ uint32_t smem_u32(const void* p) {
    return (uint32_t)__cvta_generic_to_shared(p);
}
__device__ __forceinline__ void mbar_init(uint32_t a, uint32_t cnt) {
    asm volatile("mbarrier.init.shared::cta.b64 [%0], %1;" :: "r"(a), "r"(cnt) : "memory");
}
__device__ __forceinline__ void mbar_arrive_expect(uint32_t a, uint32_t bytes) {
    asm volatile("mbarrier.arrive.expect_tx.shared::cta.b64 _, [%0], %1;"
                 :: "r"(a), "r"(bytes) : "memory");
}
__device__ __forceinline__ void bulk_g2s(uint32_t dst, const void* src,
                                         uint32_t bytes, uint32_t mbar) {
    asm volatile("cp.async.bulk.shared::cta.global.mbarrier::complete_tx::bytes "
                 "[%0], [%1], %2, [%3];"
                 :: "r"(dst), "l"(src), "r"(bytes), "r"(mbar) : "memory");
}
__device__ __forceinline__ void mbar_wait(uint32_t a, uint32_t parity) {
    asm volatile(
        "{\n\t.reg .pred P;\n\t"
        "WAIT_%=:\n\t"
        "mbarrier.try_wait.parity.shared::cta.b64 P, [%0], %1;\n\t"
        "@!P bra WAIT_%=;\n\t}"
        :: "r"(a), "r"(parity) : "memory");
}

// ---------------------------------------------------------------------------
// Kernel 2: fused persistent kernel. Each CTA handles slice-pairs
// (same slice index in tensor a and b), computes d_a and d_b, accumulates
// |d_a - d_b| locally, one atomicAdd per CTA; last CTA writes the loss.
// 5-deep 32KB cp.async.bulk ring; conflict-free stride-1 pass 2.
// ---------------------------------------------------------------------------
__global__ void __launch_bounds__(NTH, 1) loss_kernel(const float* __restrict__ a,
                                                      const float* __restrict__ b,
                                                      float* __restrict__ out) {
    extern __shared__ float smem[];
    float* tab  = smem;                        // 16384 floats (64 KB)
    float* ring = smem + HW;                   // NRING * 8192 floats

    __shared__ __align__(8) unsigned long long mbar_store[NRING];
    __shared__ float s_v[16];
    __shared__ int   s_i[16];
    __shared__ float s_s[16];
    __shared__ int   s_c[16];

    const int t = threadIdx.x;
    const int warp = t >> 5, lane = t & 31;
    const int cta = blockIdx.x;
    const int npair  = (NSLICE - cta + NCTA - 1) / NCTA;   // 7 or 8
    const int nslice = 2 * npair;
    const int nchunk = 2 * nslice;                          // >= 28 > NRING

    uint32_t mb[NRING];
    #pragma unroll
    for (int r = 0; r < NRING; ++r) mb[r] = smem_u32(&mbar_store[r]);
    if (t == 0) {
        #pragma unroll
        for (int r = 0; r < NRING; ++r) mbar_init(mb[r], 1);
    }
    __syncthreads();

    // chunk k: pair (k>>2), tensor ((k>>1)&1), half (k&1)
    auto chunk_src = [&](int k) -> const float* {
        int p = k >> 2, which = (k >> 1) & 1, half = k & 1;
        const float* base = which ? b : a;
        return base + (size_t)(cta + p * NCTA) * HW + (size_t)half * CHUNK_FLOATS;
    };

    // prefill all 5 slots
    if (t == 0) {
        #pragma unroll
        for (int k = 0; k < NRING; ++k) {
            mbar_arrive_expect(mb[k], CHUNK_BYTES);
            bulk_g2s(smem_u32(ring + k * CHUNK_FLOATS), chunk_src(k),
                     CHUNK_BYTES, mb[k]);
        }
    }

    // table -> smem (overlaps prefill; consumed only after first reduction sync)
    {
        const float4* gt = (const float4*)g_table;
        float4* st = (float4*)tab;
        #pragma unroll
        for (int r = 0; r < 8; ++r) st[r * NTH + t] = __ldg(gt + r * NTH + t);
    }

    float acc = 0.0f;       // meaningful in t==0 only
    float prev_d = 0.0f;

    for (int m = 0; m < nslice; ++m) {
        const int k0 = 2 * m, k1 = 2 * m + 1;
        const int slot0 = k0 % NRING, slot1 = k1 % NRING;

        // ---------- pass 1: max + lowest flat index over both chunks --------
        float vmax = -1e30f;
        int   vidx = 0x7fffffff;

        mbar_wait(mb[slot0], (k0 / NRING) & 1);
        {
            const float4* bf4 = (const float4*)(ring + slot0 * CHUNK_FLOATS);
            #pragma unroll
            for (int r = 0; r < 4; ++r) {
                float4 x = bf4[r * NTH + t];
                int e = (r * NTH + t) << 2;
                float mx = fmaxf(fmaxf(x.x, x.y), fmaxf(x.z, x.w));
                if (mx > vmax) {
                    vmax = mx;
                    vidx = e + ((x.x == mx) ? 0 : (x.y == mx) ? 1 : (x.z == mx) ? 2 : 3);
                }
            }
        }
        mbar_wait(mb[slot1], (k1 / NRING) & 1);
        {
            const float4* bf4 = (const float4*)(ring + slot1 * CHUNK_FLOATS);
            #pragma unroll
            for (int r = 0; r < 4; ++r) {
                float4 x = bf4[r * NTH + t];
                int e = CHUNK_FLOATS + ((r * NTH + t) << 2);
                float mx = fmaxf(fmaxf(x.x, x.y), fmaxf(x.z, x.w));
                if (mx > vmax) {
                    vmax = mx;
                    vidx = e + ((x.x == mx) ? 0 : (x.y == mx) ? 1 : (x.z == mx) ? 2 : 3);
                }
            }
        }
        #pragma unroll
        for (int off = 16; off > 0; off >>= 1) {
            float ov = __shfl_down_sync(0xffffffffu, vmax, off);
            int   oi = __shfl_down_sync(0xffffffffu, vidx, off);
            if (ov > vmax || (ov == vmax && oi < vidx)) { vmax = ov; vidx = oi; }
        }
        if (lane == 0) { s_v[warp] = vmax; s_i[warp] = vidx; }
        __syncthreads();
        float bv = s_v[0]; int bi = s_i[0];
        #pragma unroll
        for (int w = 1; w < 16; ++w) {
            float wv = s_v[w]; int wi = s_i[w];
            if (wv > bv || (wv == bv && wi < bi)) { bv = wv; bi = wi; }
        }

        // ---------- pass 2: stride-1 conflict-free masked distance sum -------
        const float thr = bv * 0.5f;
        const int ym = bi >> 7;
        const int xm = bi & 127;

        // gather byte-offsets are y-invariant: computed once per slice
        uint32_t gofs0 = (uint32_t)::abs(lane      - xm) << 2;
        uint32_t gofs1 = (uint32_t)::abs(lane + 32 - xm) << 2;
        uint32_t gofs2 = (uint32_t)::abs(lane + 64 - xm) << 2;
        uint32_t gofs3 = (uint32_t)::abs(lane + 96 - xm) << 2;

        // warp w owns rows 8w..8w+7; rows 0-63 in slot0, 64-127 in slot1
        const float* vbase = (warp < 8)
            ? ring + slot0 * CHUNK_FLOATS + (warp << 3) * 128 + lane
            : ring + slot1 * CHUNK_FLOATS + ((warp << 3) - 64) * 128 + lane;
        const int y0 = warp << 3;

        float sum = 0.0f;
        int   cnt = 0;
        #pragma unroll
        for (int rr = 0; rr < 8; ++rr) {
            const int ady = ::abs(y0 + rr - ym);
            const char* trow = (const char*)(tab + (ady << 7));
            const float* vrow = vbase + rr * 128;
            float v0 = vrow[0],  v1 = vrow[32], v2 = vrow[64], v3 = vrow[96];
            float d0 = *(const float*)(trow + gofs0);
            float d1 = *(const float*)(trow + gofs1);
            float d2 = *(const float*)(trow + gofs2);
            float d3 = *(const float*)(trow + gofs3);
            bool m0 = v0 > thr, m1 = v1 > thr, m2 = v2 > thr, m3 = v3 > thr;
            sum += m0 ? d0 : 0.0f;  cnt += m0;
            sum += m1 ? d1 : 0.0f;  cnt += m1;
            sum += m2 ? d2 : 0.0f;  cnt += m2;
            sum += m3 ? d3 : 0.0f;  cnt += m3;
        }
        #pragma unroll
        for (int off = 16; off > 0; off >>= 1) {
            sum += __shfl_down_sync(0xffffffffu, sum, off);
            cnt += __shfl_down_sync(0xffffffffu, cnt, off);
        }
        if (lane == 0) { s_s[warp] = sum; s_c[warp] = cnt; }
        __syncthreads();          // all pass-2 reads of slot0/slot1 complete

        if (t == 0) {
            // refill freed slots (arm happens >= 1 barrier before any wait on them)
            if (k0 + NRING < nchunk) {
                mbar_arrive_expect(mb[slot0], CHUNK_BYTES);
                bulk_g2s(smem_u32(ring + slot0 * CHUNK_FLOATS),
                         chunk_src(k0 + NRING), CHUNK_BYTES, mb[slot0]);
            }
            if (k1 + NRING < nchunk) {
                mbar_arrive_expect(mb[slot1], CHUNK_BYTES);
                bulk_g2s(smem_u32(ring + slot1 * CHUNK_FLOATS),
                         chunk_src(k1 + NRING), CHUNK_BYTES, mb[slot1]);
            }
            float S = 0.0f; int C = 0;
            #pragma unroll
            for (int w = 0; w < 16; ++w) { S += s_s[w]; C += s_c[w]; }
            float d;
            if (bv > 0.0f) {
                d = (C > 0) ? (S / (float)C) / MAX_DIST : 1.0f;
            } else {
                d = 0.0f;
            }
            if (m & 1) acc += fabsf(prev_d - d);   // pair complete: |d_a - d_b|
            else       prev_d = d;
        }
        __syncthreads();          // protect s_v/s_s reuse + order refill arms
    }

    // ---------- fused finalize: one atomic per CTA, last CTA writes out -----
    if (t == 0) {
        atomicAdd(&g_acc, acc);
        __threadfence();
        unsigned int v = atomicAdd(&g_done, 1u);
        if (v == NCTA - 1) {
            float total = atomicAdd(&g_acc, 0.0f);   // L2-serialized read
            out[0] = total / 17.0f / 64.0f;
        }
    }
}

extern "C" void kernel_launch(void* const* d_in, const int* in_sizes, int n_in,
                              void* d_out, int out_size) {
    const float* a = (const float*)d_in[0];   // output heatmaps [64,17,128,128] f32
    const float* b = (const float*)d_in[1];   // target heatmaps [64,17,128,128] f32
    (void)in_sizes; (void)n_in; (void)out_size;

    const int smem_bytes = (HW + NRING * CHUNK_FLOATS) * 4;   // 224 KB

    static bool attr_set = false;
    if (!attr_set) {
        cudaFuncSetAttribute(loss_kernel,
                             cudaFuncAttributeMaxDynamicSharedMemorySize, smem_bytes);
        attr_set = true;
    }

    build_table_kernel<<<64, 256>>>();
    loss_kernel<<<NCTA, NTH, smem_bytes>>>(a, b, (float*)d_out);
}

// round 7
// speedup vs baseline: 1.3425x; 1.0520x over previous
#include <cuda_runtime.h>
#include <math.h>
#include <stdint.h>

#define NSLICE 1088          // 64 * 17 slices per tensor
#define HW     16384         // 128 * 128
#define MAX_DIST 181.02f
#define NCTA 272             // 1088 / 4: exactly 4 pairs (8 slices) per CTA
#define NTH  512
#define CHUNK_FLOATS 8192    // 32 KB chunks, 2 per slice (rows 0-63 / 64-127)
#define CHUNK_BYTES  32768
#define NRING 3              // 96 KB ring -> 2 CTAs/SM

__device__ float g_acc = 0.0f;       // global loss accumulator (reset by last CTA)
__device__ unsigned int g_done = 0u; // CTA completion counter (reset by last CTA)

// ---------------------------------------------------------------------------
// mbarrier / bulk-copy / math helpers
// ---------------------------------------------------------------------------
__device__ __forceinline__ uint32_t smem_u32(const void* p) {
    return (uint32_t)__cvta_generic_to_shared(p);
}
__device__ __forceinline__ void mbar_init(uint32_t a, uint32_t cnt) {
    asm volatile("mbarrier.init.shared::cta.b64 [%0], %1;" :: "r"(a), "r"(cnt) : "memory");
}
__device__ __forceinline__ void mbar_arrive_expect(uint32_t a, uint32_t bytes) {
    asm volatile("mbarrier.arrive.expect_tx.shared::cta.b64 _, [%0], %1;"
                 :: "r"(a), "r"(bytes) : "memory");
}
__device__ __forceinline__ void bulk_g2s(uint32_t dst, const void* src,
                                         uint32_t bytes, uint32_t mbar) {
    asm volatile("cp.async.bulk.shared::cta.global.mbarrier::complete_tx::bytes "
                 "[%0], [%1], %2, [%3];"
                 :: "r"(dst), "l"(src), "r"(bytes), "r"(mbar) : "memory");
}
__device__ __forceinline__ void mbar_wait(uint32_t a, uint32_t parity) {
    asm volatile(
        "{\n\t.reg .pred P;\n\t"
        "WAIT_%=:\n\t"
        "mbarrier.try_wait.parity.shared::cta.b64 P, [%0], %1;\n\t"
        "@!P bra WAIT_%=;\n\t}"
        :: "r"(a), "r"(parity) : "memory");
}
__device__ __forceinline__ float fsqrt_approx(float x) {
    float r;
    asm("sqrt.approx.f32 %0, %1;" : "=f"(r) : "f"(x));
    return r;
}

// ---------------------------------------------------------------------------
// Fused persistent kernel, 2 CTAs/SM. Each CTA handles 4 slice-pairs
// (same slice index in tensors a and b): pass 1 max/argmax, pass 2 masked
// mean distance with inline MUFU sqrt (no table). |d_a - d_b| accumulated
// locally; one atomicAdd per CTA; last CTA writes the loss and resets state.
// ---------------------------------------------------------------------------
__global__ void __launch_bounds__(NTH, 2) loss_kernel(const float* __restrict__ a,
                                                      const float* __restrict__ b,
                                                      float* __restrict__ out) {
    extern __shared__ float ring[];            // NRING * 8192 floats (96 KB)

    __shared__ __align__(8) unsigned long long mbar_store[NRING];
    __shared__ float s_v[16];
    __shared__ int   s_i[16];
    __shared__ float s_s[16];
    __shared__ int   s_c[16];

    const int t = threadIdx.x;
    const int warp = t >> 5, lane = t & 31;
    const int cta = blockIdx.x;
    const int nslice = 8;                      // 4 pairs exactly
    const int nchunk = 16;

    uint32_t mb[NRING];
    #pragma unroll
    for (int r = 0; r < NRING; ++r) mb[r] = smem_u32(&mbar_store[r]);
    if (t == 0) {
        #pragma unroll
        for (int r = 0; r < NRING; ++r) mbar_init(mb[r], 1);
    }
    __syncthreads();

    // chunk k: pair (k>>2), tensor ((k>>1)&1), half (k&1)
    auto chunk_src = [&](int k) -> const float* {
        int p = k >> 2, which = (k >> 1) & 1, half = k & 1;
        const float* base = which ? b : a;
        return base + (size_t)(cta + p * NCTA) * HW + (size_t)half * CHUNK_FLOATS;
    };

    // prefill all ring slots
    if (t == 0) {
        #pragma unroll
        for (int k = 0; k < NRING; ++k) {
            mbar_arrive_expect(mb[k], CHUNK_BYTES);
            bulk_g2s(smem_u32(ring + k * CHUNK_FLOATS), chunk_src(k),
                     CHUNK_BYTES, mb[k]);
        }
    }

    float acc = 0.0f;       // meaningful in t==0 only
    float prev_d = 0.0f;

    for (int m = 0; m < nslice; ++m) {
        const int k0 = 2 * m, k1 = 2 * m + 1;
        const int slot0 = k0 % NRING, slot1 = k1 % NRING;

        // ---------- pass 1: max + lowest flat index over both chunks --------
        float vmax = -1e30f;
        int   vidx = 0x7fffffff;

        mbar_wait(mb[slot0], (k0 / NRING) & 1);
        {
            const float4* bf4 = (const float4*)(ring + slot0 * CHUNK_FLOATS);
            #pragma unroll
            for (int r = 0; r < 4; ++r) {
                float4 x = bf4[r * NTH + t];
                int e = (r * NTH + t) << 2;
                float mx = fmaxf(fmaxf(x.x, x.y), fmaxf(x.z, x.w));
                if (mx > vmax) {
                    vmax = mx;
                    vidx = e + ((x.x == mx) ? 0 : (x.y == mx) ? 1 : (x.z == mx) ? 2 : 3);
                }
            }
        }
        mbar_wait(mb[slot1], (k1 / NRING) & 1);
        {
            const float4* bf4 = (const float4*)(ring + slot1 * CHUNK_FLOATS);
            #pragma unroll
            for (int r = 0; r < 4; ++r) {
                float4 x = bf4[r * NTH + t];
                int e = CHUNK_FLOATS + ((r * NTH + t) << 2);
                float mx = fmaxf(fmaxf(x.x, x.y), fmaxf(x.z, x.w));
                if (mx > vmax) {
                    vmax = mx;
                    vidx = e + ((x.x == mx) ? 0 : (x.y == mx) ? 1 : (x.z == mx) ? 2 : 3);
                }
            }
        }
        #pragma unroll
        for (int off = 16; off > 0; off >>= 1) {
            float ov = __shfl_down_sync(0xffffffffu, vmax, off);
            int   oi = __shfl_down_sync(0xffffffffu, vidx, off);
            if (ov > vmax || (ov == vmax && oi < vidx)) { vmax = ov; vidx = oi; }
        }
        if (lane == 0) { s_v[warp] = vmax; s_i[warp] = vidx; }
        __syncthreads();
        float bv = s_v[0]; int bi = s_i[0];
        #pragma unroll
        for (int w = 1; w < 16; ++w) {
            float wv = s_v[w]; int wi = s_i[w];
            if (wv > bv || (wv == bv && wi < bi)) { bv = wv; bi = wi; }
        }

        // ---------- pass 2: stride-1 values + inline sqrt distances ---------
        const float thr = bv * 0.5f;
        const int ym = bi >> 7;
        const int xm = bi & 127;

        // dx^2 per thread is slice-invariant (x = lane + 32c)
        const int dx0 = lane      - xm, dx1 = lane + 32 - xm;
        const int dx2 = lane + 64 - xm, dx3 = lane + 96 - xm;
        const float fdx2_0 = (float)(dx0 * dx0);
        const float fdx2_1 = (float)(dx1 * dx1);
        const float fdx2_2 = (float)(dx2 * dx2);
        const float fdx2_3 = (float)(dx3 * dx3);

        // warp w owns rows 8w..8w+7; rows 0-63 in slot0, 64-127 in slot1
        const float* vbase = (warp < 8)
            ? ring + slot0 * CHUNK_FLOATS + (warp << 3) * 128 + lane
            : ring + slot1 * CHUNK_FLOATS + ((warp << 3) - 64) * 128 + lane;
        const int y0 = warp << 3;

        float sum = 0.0f;
        int   cnt = 0;
        #pragma unroll
        for (int rr = 0; rr < 8; ++rr) {
            const int dy = y0 + rr - ym;
            const float fdy2 = (float)(dy * dy);
            const float* vrow = vbase + rr * 128;
            float v0 = vrow[0],  v1 = vrow[32], v2 = vrow[64], v3 = vrow[96];
            float d0 = fsqrt_approx(fdy2 + fdx2_0);
            float d1 = fsqrt_approx(fdy2 + fdx2_1);
            float d2 = fsqrt_approx(fdy2 + fdx2_2);
            float d3 = fsqrt_approx(fdy2 + fdx2_3);
            bool m0 = v0 > thr, m1 = v1 > thr, m2 = v2 > thr, m3 = v3 > thr;
            sum += m0 ? d0 : 0.0f;  cnt += m0;
            sum += m1 ? d1 : 0.0f;  cnt += m1;
            sum += m2 ? d2 : 0.0f;  cnt += m2;
            sum += m3 ? d3 : 0.0f;  cnt += m3;
        }
        #pragma unroll
        for (int off = 16; off > 0; off >>= 1) {
            sum += __shfl_down_sync(0xffffffffu, sum, off);
            cnt += __shfl_down_sync(0xffffffffu, cnt, off);
        }
        if (lane == 0) { s_s[warp] = sum; s_c[warp] = cnt; }
        __syncthreads();          // all pass-2 reads of slot0/slot1 complete

        if (t == 0) {
            // refill freed slots
            if (k0 + NRING < nchunk) {
                mbar_arrive_expect(mb[slot0], CHUNK_BYTES);
                bulk_g2s(smem_u32(ring + slot0 * CHUNK_FLOATS),
                         chunk_src(k0 + NRING), CHUNK_BYTES, mb[slot0]);
            }
            if (k1 + NRING < nchunk) {
                mbar_arrive_expect(mb[slot1], CHUNK_BYTES);
                bulk_g2s(smem_u32(ring + slot1 * CHUNK_FLOATS),
                         chunk_src(k1 + NRING), CHUNK_BYTES, mb[slot1]);
            }
            float S = 0.0f; int C = 0;
            #pragma unroll
            for (int w = 0; w < 16; ++w) { S += s_s[w]; C += s_c[w]; }
            float d;
            if (bv > 0.0f) {
                d = (C > 0) ? (S / (float)C) / MAX_DIST : 1.0f;
            } else {
                d = 0.0f;
            }
            if (m & 1) acc += fabsf(prev_d - d);   // pair complete: |d_a - d_b|
            else       prev_d = d;
        }
        __syncthreads();          // protect s_v/s_s reuse + order refill arms
    }

    // ---------- fused finalize: one atomic per CTA; last CTA writes + resets
    if (t == 0) {
        atomicAdd(&g_acc, acc);
        __threadfence();
        unsigned int v = atomicAdd(&g_done, 1u);
        if (v == NCTA - 1) {
            float total = atomicAdd(&g_acc, 0.0f);   // serialized read after all adds
            out[0] = total / 17.0f / 64.0f;
            g_acc = 0.0f;                            // restore invariant for next run
            __threadfence();
            g_done = 0u;
        }
    }
}

extern "C" void kernel_launch(void* const* d_in, const int* in_sizes, int n_in,
                              void* d_out, int out_size) {
    const float* a = (const float*)d_in[0];   // output heatmaps [64,17,128,128] f32
    const float* b = (const float*)d_in[1];   // target heatmaps [64,17,128,128] f32
    (void)in_sizes; (void)n_in; (void)out_size;

    const int smem_bytes = NRING * CHUNK_BYTES;   // 96 KB

    static bool attr_set = false;
    if (!attr_set) {
        cudaFuncSetAttribute(loss_kernel,
                             cudaFuncAttributeMaxDynamicSharedMemorySize, smem_bytes);
        attr_set = true;
    }

    loss_kernel<<<NCTA, NTH, smem_bytes>>>(a, b, (float*)d_out);
}

// round 8
// speedup vs baseline: 1.4868x; 1.1075x over previous
#include <cuda_runtime.h>
#include <math.h>
#include <stdint.h>

#define NSLICE 1088          // 64 * 17 slices per tensor
#define HW     16384         // 128 * 128
#define MAX_DIST 181.02f
#define NCTA 272             // 1088 / 4: exactly 4 pairs (8 slices) per CTA
#define NTH  1024
#define CHUNK_FLOATS 8192    // 32 KB chunks, 2 per slice (rows 0-63 / 64-127)
#define CHUNK_BYTES  32768
#define NRING 3              // 96 KB ring -> 2 CTAs/SM, 64 warps/SM

__device__ float g_acc = 0.0f;       // global loss accumulator (reset by last CTA)
__device__ unsigned int g_done = 0u; // CTA completion counter (reset by last CTA)

// ---------------------------------------------------------------------------
// mbarrier / bulk-copy / math helpers
// ---------------------------------------------------------------------------
__device__ __forceinline__ uint32_t smem_u32(const void* p) {
    return (uint32_t)__cvta_generic_to_shared(p);
}
__device__ __forceinline__ void mbar_init(uint32_t a, uint32_t cnt) {
    asm volatile("mbarrier.init.shared::cta.b64 [%0], %1;" :: "r"(a), "r"(cnt) : "memory");
}
__device__ __forceinline__ void mbar_arrive_expect(uint32_t a, uint32_t bytes) {
    asm volatile("mbarrier.arrive.expect_tx.shared::cta.b64 _, [%0], %1;"
                 :: "r"(a), "r"(bytes) : "memory");
}
__device__ __forceinline__ void bulk_g2s(uint32_t dst, const void* src,
                                         uint32_t bytes, uint32_t mbar) {
    asm volatile("cp.async.bulk.shared::cta.global.mbarrier::complete_tx::bytes "
                 "[%0], [%1], %2, [%3];"
                 :: "r"(dst), "l"(src), "r"(bytes), "r"(mbar) : "memory");
}
__device__ __forceinline__ void mbar_wait(uint32_t a, uint32_t parity) {
    asm volatile(
        "{\n\t.reg .pred P;\n\t"
        "WAIT_%=:\n\t"
        "mbarrier.try_wait.parity.shared::cta.b64 P, [%0], %1;\n\t"
        "@!P bra WAIT_%=;\n\t}"
        :: "r"(a), "r"(parity) : "memory");
}
__device__ __forceinline__ float fsqrt_approx(float x) {
    float r;
    asm("sqrt.approx.f32 %0, %1;" : "=f"(r) : "f"(x));
    return r;
}

// ---------------------------------------------------------------------------
// Fused persistent kernel, 1024 threads, 2 CTAs/SM (64 warps/SM).
// Pass 1: value-only max (FMNMX); argmax found by rare equality rescan +
// shared atomicMin (exact lowest-flat-index tie-break). Pass 2: masked mean
// distance with inline MUFU sqrt. One atomicAdd per CTA; last CTA finalizes.
// ---------------------------------------------------------------------------
__global__ void __launch_bounds__(NTH, 2) loss_kernel(const float* __restrict__ a,
                                                      const float* __restrict__ b,
                                                      float* __restrict__ out) {
    extern __shared__ float ring[];            // NRING * 8192 floats (96 KB)

    __shared__ __align__(8) unsigned long long mbar_store[NRING];
    __shared__ float s_v[32];
    __shared__ float s_s[32];
    __shared__ int   s_c[32];
    __shared__ float s_bv;
    __shared__ int   s_idx;

    const int t = threadIdx.x;
    const int warp = t >> 5, lane = t & 31;
    const int cta = blockIdx.x;
    const int nchunk = 16;                     // 4 pairs = 8 slices = 16 chunks

    uint32_t mb[NRING];
    #pragma unroll
    for (int r = 0; r < NRING; ++r) mb[r] = smem_u32(&mbar_store[r]);
    if (t == 0) {
        #pragma unroll
        for (int r = 0; r < NRING; ++r) mbar_init(mb[r], 1);
    }
    __syncthreads();

    // chunk k: pair (k>>2), tensor ((k>>1)&1), half (k&1)
    auto chunk_src = [&](int k) -> const float* {
        int p = k >> 2, which = (k >> 1) & 1, half = k & 1;
        const float* base = which ? b : a;
        return base + (size_t)(cta + p * NCTA) * HW + (size_t)half * CHUNK_FLOATS;
    };

    if (t == 0) {                              // prefill all ring slots
        #pragma unroll
        for (int k = 0; k < NRING; ++k) {
            mbar_arrive_expect(mb[k], CHUNK_BYTES);
            bulk_g2s(smem_u32(ring + k * CHUNK_FLOATS), chunk_src(k),
                     CHUNK_BYTES, mb[k]);
        }
    }

    float acc = 0.0f;       // meaningful in t==0 only
    float prev_d = 0.0f;

    for (int m = 0; m < 8; ++m) {
        const int k0 = 2 * m, k1 = 2 * m + 1;
        const int slot0 = k0 % NRING, slot1 = k1 % NRING;

        // ---------- pass 1: value-only max over both chunks ------------------
        float mymax = -1e30f;
        mbar_wait(mb[slot0], (k0 / NRING) & 1);
        {
            const float4* p = (const float4*)(ring + slot0 * CHUNK_FLOATS);
            float4 q;
            q = p[t];       mymax = fmaxf(mymax, fmaxf(fmaxf(q.x, q.y), fmaxf(q.z, q.w)));
            q = p[NTH + t]; mymax = fmaxf(mymax, fmaxf(fmaxf(q.x, q.y), fmaxf(q.z, q.w)));
        }
        mbar_wait(mb[slot1], (k1 / NRING) & 1);
        {
            const float4* p = (const float4*)(ring + slot1 * CHUNK_FLOATS);
            float4 q;
            q = p[t];       mymax = fmaxf(mymax, fmaxf(fmaxf(q.x, q.y), fmaxf(q.z, q.w)));
            q = p[NTH + t]; mymax = fmaxf(mymax, fmaxf(fmaxf(q.x, q.y), fmaxf(q.z, q.w)));
        }
        float wmax = mymax;
        #pragma unroll
        for (int off = 16; off > 0; off >>= 1)
            wmax = fmaxf(wmax, __shfl_xor_sync(0xffffffffu, wmax, off));
        if (lane == 0) s_v[warp] = wmax;
        __syncthreads();                       // S1
        if (warp == 0) {
            float x = s_v[lane];               // exactly 32 warp maxima
            #pragma unroll
            for (int off = 16; off > 0; off >>= 1)
                x = fmaxf(x, __shfl_xor_sync(0xffffffffu, x, off));
            if (lane == 0) { s_bv = x; s_idx = 0x7fffffff; }
        }
        __syncthreads();                       // S2
        const float bv = s_bv;

        // rare path: threads holding the max rescan their 16 smem values
        if (mymax == bv) {
            int my_e = 0x7fffffff;
            #pragma unroll
            for (int c = 1; c >= 0; --c) {     // descending: final write = lowest e
                const int slot = c ? slot1 : slot0;
                #pragma unroll
                for (int r = 1; r >= 0; --r) {
                    const float* q = ring + slot * CHUNK_FLOATS + ((r * NTH + t) << 2);
                    const int e = c * CHUNK_FLOATS + ((r * NTH + t) << 2);
                    if (q[3] == bv) my_e = e + 3;
                    if (q[2] == bv) my_e = e + 2;
                    if (q[1] == bv) my_e = e + 1;
                    if (q[0] == bv) my_e = e;
                }
            }
            atomicMin(&s_idx, my_e);
        }
        __syncthreads();                       // S3
        const int bi = s_idx;

        // ---------- pass 2: stride-1 values + inline sqrt distances ----------
        const float thr = bv * 0.5f;
        const int ym = bi >> 7;
        const int xm = bi & 127;

        const int dx0 = lane      - xm, dx1 = lane + 32 - xm;
        const int dx2 = lane + 64 - xm, dx3 = lane + 96 - xm;
        const float fdx2_0 = (float)(dx0 * dx0);
        const float fdx2_1 = (float)(dx1 * dx1);
        const float fdx2_2 = (float)(dx2 * dx2);
        const float fdx2_3 = (float)(dx3 * dx3);

        // warp w owns rows 4w..4w+3; rows 0-63 in slot0, 64-127 in slot1
        const int y0 = warp << 2;
        const float* vbase = (warp < 16)
            ? ring + slot0 * CHUNK_FLOATS + (y0 << 7) + lane
            : ring + slot1 * CHUNK_FLOATS + ((y0 - 64) << 7) + lane;

        float sum = 0.0f;
        int   cnt = 0;
        #pragma unroll
        for (int rr = 0; rr < 4; ++rr) {
            const int dy = y0 + rr - ym;
            const float fdy2 = (float)(dy * dy);
            const float* vrow = vbase + rr * 128;
            float v0 = vrow[0],  v1 = vrow[32], v2 = vrow[64], v3 = vrow[96];
            float d0 = fsqrt_approx(fdy2 + fdx2_0);
            float d1 = fsqrt_approx(fdy2 + fdx2_1);
            float d2 = fsqrt_approx(fdy2 + fdx2_2);
            float d3 = fsqrt_approx(fdy2 + fdx2_3);
            if (v0 > thr) { sum += d0; ++cnt; }
            if (v1 > thr) { sum += d1; ++cnt; }
            if (v2 > thr) { sum += d2; ++cnt; }
            if (v3 > thr) { sum += d3; ++cnt; }
        }
        #pragma unroll
        for (int off = 16; off > 0; off >>= 1) {
            sum += __shfl_down_sync(0xffffffffu, sum, off);
            cnt += __shfl_down_sync(0xffffffffu, cnt, off);
        }
        if (lane == 0) { s_s[warp] = sum; s_c[warp] = cnt; }
        __syncthreads();                       // S4: all pass-2 reads complete

        if (t == 0) {
            // refill freed slots (waiters poll parity; late arm is safe)
            if (k0 + NRING < nchunk) {
                mbar_arrive_expect(mb[slot0], CHUNK_BYTES);
                bulk_g2s(smem_u32(ring + slot0 * CHUNK_FLOATS),
                         chunk_src(k0 + NRING), CHUNK_BYTES, mb[slot0]);
            }
            if (k1 + NRING < nchunk) {
                mbar_arrive_expect(mb[slot1], CHUNK_BYTES);
                bulk_g2s(smem_u32(ring + slot1 * CHUNK_FLOATS),
                         chunk_src(k1 + NRING), CHUNK_BYTES, mb[slot1]);
            }
            float S = 0.0f; int C = 0;
            #pragma unroll
            for (int w = 0; w < 32; ++w) { S += s_s[w]; C += s_c[w]; }
            float d;
            if (bv > 0.0f) {
                d = (C > 0) ? (S / (float)C) / MAX_DIST : 1.0f;
            } else {
                d = 0.0f;
            }
            if (m & 1) acc += fabsf(prev_d - d);   // pair complete: |d_a - d_b|
            else       prev_d = d;
        }
        // no extra barrier needed: s_s/s_v rewrites are separated from t0's
        // reads by S1..S4 of the next iteration.
    }

    // ---------- fused finalize: one atomic per CTA; last CTA writes + resets
    if (t == 0) {
        atomicAdd(&g_acc, acc);
        __threadfence();
        unsigned int v = atomicAdd(&g_done, 1u);
        if (v == NCTA - 1) {
            float total = atomicAdd(&g_acc, 0.0f);   // serialized read after all adds
            out[0] = total / 17.0f / 64.0f;
            g_acc = 0.0f;                            // restore invariant for next run
            __threadfence();
            g_done = 0u;
        }
    }
}

extern "C" void kernel_launch(void* const* d_in, const int* in_sizes, int n_in,
                              void* d_out, int out_size) {
    const float* a = (const float*)d_in[0];   // output heatmaps [64,17,128,128] f32
    const float* b = (const float*)d_in[1];   // target heatmaps [64,17,128,128] f32
    (void)in_sizes; (void)n_in; (void)out_size;

    const int smem_bytes = NRING * CHUNK_BYTES;   // 96 KB

    static bool attr_set = false;
    if (!attr_set) {
        cudaFuncSetAttribute(loss_kernel,
                             cudaFuncAttributeMaxDynamicSharedMemorySize, smem_bytes);
        attr_set = true;
    }

    loss_kernel<<<NCTA, NTH, smem_bytes>>>(a, b, (float*)d_out);
}